// round 3
// baseline (speedup 1.0000x reference)
#include <cuda_runtime.h>

#define NB      8
#define NHEADS  12
#define HH      24
#define SEQ     576
#define DIM     64
#define NPOS    24
#define BATCH   96
#define KPAD    26
#define LISZ    (BATCH * SEQ * NPOS)

// Scratch
__device__ __align__(16) float g_Vx[LISZ];
__device__ __align__(16) float g_Vy[LISZ];
__device__ __align__(16) float g_Li[2 * LISZ];   // [path][bh][s][p]

__device__ __forceinline__ float sigmoidf_(float x) {
    return 1.0f / (1.0f + __expf(-x));
}

__device__ __forceinline__ unsigned long long fma2(unsigned long long a,
                                                   unsigned long long b,
                                                   unsigned long long c) {
    unsigned long long d;
    asm("fma.rn.f32x2 %0, %1, %2, %3;" : "=l"(d) : "l"(a), "l"(b), "l"(c));
    return d;
}

__device__ __forceinline__ unsigned long long pack2(float lo, float hi) {
    unsigned long long r;
    asm("mov.b64 %0, {%1, %2};" : "=l"(r) : "f"(lo), "f"(hi));
    return r;
}

__device__ __forceinline__ float fsqrt_approx(float x) {
    float r;
    asm("sqrt.approx.f32 %0, %1;" : "=f"(r) : "f"(x));
    return r;
}

// ---------------------------------------------------------------------------
// Kernel 1a: Li[path][bh][srow][p] = query[b,m,srow,:] . pe_path[:,p]
// grid (9, 96); block 256. 64 rows per block; thread = (row r = t>>2, g = t&3)
// g -> path = g>>1, half = g&1 (12 p-values). Register-tiled, fma2.
// pe_s layout: [d][g*12 + p'] with g-chunks at word offsets {0,12,24,36}
// (bank-disjoint for the 3 LDS.128 per d).
// ---------------------------------------------------------------------------
__global__ void __launch_bounds__(256) li_kernel(
    const float* __restrict__ query,   // [8,12,576,64]
    const float* __restrict__ pex,     // [64,24]
    const float* __restrict__ pey)     // [64,24]
{
    __shared__ __align__(16) float q_s[64 * 65];
    __shared__ __align__(16) float pe_s[64 * 48];

    int s0 = blockIdx.x * 64;
    int bh = blockIdx.y;
    int t  = threadIdx.x;

    // pe fill: pe_s[d*48 + (pa*2+half)*12 + p'] = pe_pa[d*24 + half*12 + p']
    for (int idx = t; idx < 2 * DIM * NPOS; idx += 256) {
        int pa = idx >> 10;              // idx / 1536
        int r  = idx & 1023;             // idx % 1536... careful: 1536 not pow2
        if (idx >= 1536) { pa = 1; r = idx - 1536; } else { pa = 0; r = idx; }
        int d = r / 24, c = r % 24;
        int half = c / 12, pp = c % 12;
        pe_s[d * 48 + (pa * 2 + half) * 12 + pp] = (pa ? pey : pex)[r];
    }

    // q fill: rows s0..s0+63 contiguous
    const float* qb = query + ((size_t)bh * SEQ + s0) * DIM;
    for (int idx = t; idx < 64 * DIM; idx += 256) {
        int row = idx >> 6, d = idx & 63;
        q_s[row * 65 + d] = qb[idx];
    }
    __syncthreads();

    int r = t >> 2;
    int g = t & 3;
    const float* qr  = q_s + r * 65;
    const float* per = pe_s + g * 12;

    unsigned long long acc[6];
    #pragma unroll
    for (int k = 0; k < 6; k++) acc[k] = 0ull;

    #pragma unroll 16
    for (int d = 0; d < DIM; d++) {
        float q = qr[d];
        unsigned long long qq = pack2(q, q);
        const float* p4 = per + d * 48;
        float4 v0 = *(const float4*)(p4 + 0);
        float4 v1 = *(const float4*)(p4 + 4);
        float4 v2 = *(const float4*)(p4 + 8);
        acc[0] = fma2(qq, pack2(v0.x, v0.y), acc[0]);
        acc[1] = fma2(qq, pack2(v0.z, v0.w), acc[1]);
        acc[2] = fma2(qq, pack2(v1.x, v1.y), acc[2]);
        acc[3] = fma2(qq, pack2(v1.z, v1.w), acc[3]);
        acc[4] = fma2(qq, pack2(v2.x, v2.y), acc[4]);
        acc[5] = fma2(qq, pack2(v2.z, v2.w), acc[5]);
    }

    int pa = g >> 1, half = g & 1;
    float* o = g_Li + (size_t)pa * LISZ + ((size_t)bh * SEQ + (s0 + r)) * NPOS + half * 12;
    float2* a2 = (float2*)acc;
    float4 w0 = make_float4(a2[0].x, a2[0].y, a2[1].x, a2[1].y);
    float4 w1 = make_float4(a2[2].x, a2[2].y, a2[3].x, a2[3].y);
    float4 w2 = make_float4(a2[4].x, a2[4].y, a2[5].x, a2[5].y);
    *(float4*)(o + 0) = w0;
    *(float4*)(o + 4) = w1;
    *(float4*)(o + 8) = w2;
}

// ---------------------------------------------------------------------------
// Kernel 1b: gate / suffix-scan / interp. One warp per (path, bh, srow).
// Total rows = 2*96*576 = 110592; block 256 (8 warps) -> 13824 blocks.
// ---------------------------------------------------------------------------
__global__ void __launch_bounds__(256) scan_kernel(
    const float* __restrict__ attn)    // [8,12,576,576]
{
    int t    = threadIdx.x;
    int lane = t & 31;
    int gid  = blockIdx.x * 8 + (t >> 5);

    int path = (gid >= 55296) ? 1 : 0;
    int rem  = gid - path * 55296;
    int bh   = rem / SEQ;
    int srow = rem - bh * SEQ;
    int b_q  = bh / 12;
    int m    = bh - b_q * 12;
    int a1   = srow / 24;        // s_q (x) or i (y)
    int a2   = srow - a1 * 24;   // j   (x) or s_q (y)

    const float* arow;
    int stride;
    if (!path) {
        int s_q = a1, j = a2;
        int id  = (b_q * 24 + s_q) * 12 + m;
        int b_a = id / 288;
        int hd  = (id / 24) % 12;
        int r_a = id % 24;
        arow = attn + (((size_t)(b_a * 12 + hd)) * SEQ + (size_t)(r_a * 24 + j)) * SEQ
                    + (size_t)(r_a * 24);
        stride = 1;
    } else {
        int i = a1, s_q = a2;
        int id  = (b_q * 24 + s_q) * 12 + m;
        int b_a = id / 288;
        int hd  = (id / 24) % 12;
        int r_a = id % 24;
        arow = attn + (((size_t)(b_a * 12 + hd)) * SEQ + (size_t)(i * 24 + r_a)) * SEQ
                    + (size_t)r_a;
        stride = 24;
    }

    float v = 0.0f;
    if (lane < NPOS)
        v = sigmoidf_(arow[lane * stride]);
    #pragma unroll
    for (int d = 1; d < 32; d <<= 1) {
        float tv = __shfl_down_sync(0xffffffffu, v, d);
        if (lane + d < NPOS) v += tv;
    }

    if (lane < NPOS) {
        float pp = fminf(v, (float)(NPOS - 1));
        float pf = floorf(pp);
        int   ifl = (int)pf;
        int   ic  = (int)ceilf(pp);
        float w   = pp - pf;
        const float* li = g_Li + (size_t)path * LISZ + ((size_t)bh * SEQ + srow) * NPOS;
        float val = li[ic] * w + li[ifl] * (1.0f - w);
        float* dst = (path ? g_Vy : g_Vx) + ((size_t)bh * SEQ + srow) * NPOS;
        dst[lane] = val;
    }
}

// ---------------------------------------------------------------------------
// Kernel 2: fused double-cdist + mix, symmetric tiles (unchanged from R2).
// ---------------------------------------------------------------------------
__global__ void __launch_bounds__(256) dist_kernel(
    const float* __restrict__ wxp,
    float* __restrict__ out)
{
    __shared__ __align__(16) float sA[2][64 * KPAD];
    __shared__ __align__(16) float sB[2][64 * KPAD];
    __shared__ float nA[2][64];
    __shared__ float nB[2][64];
    __shared__ float sT[64 * 65];

    int bz = blockIdx.y;
    int u = blockIdx.x;
    int ti = 0;
    #pragma unroll 1
    while (u >= (9 - ti)) { u -= (9 - ti); ti++; }
    int tj = ti + u;
    int p0 = ti * 64;
    int q0 = tj * 64;

    int t  = threadIdx.x;
    int tx = t & 15;
    int ty = t >> 4;

    #pragma unroll
    for (int s = 0; s < 2; s++) {
        const float* V = s ? g_Vy : g_Vx;
        const float4* ga = (const float4*)(V + ((size_t)bz * SEQ + p0) * NPOS);
        const float4* gb = (const float4*)(V + ((size_t)bz * SEQ + q0) * NPOS);
        for (int idx = t; idx < 64 * NPOS / 4; idx += 256) {
            float4 va = ga[idx];
            float4 vb = gb[idx];
            int r = idx / 6, c = (idx % 6) * 4;
            float* da = &sA[s][r * KPAD + c];
            da[0] = va.x; da[1] = va.y; da[2] = va.z; da[3] = va.w;
            float* db = &sB[s][r * KPAD + c];
            db[0] = vb.x; db[1] = vb.y; db[2] = vb.z; db[3] = vb.w;
        }
    }
    __syncthreads();

    {
        int s  = (t >> 7) & 1;
        int ab = (t >> 6) & 1;
        int r  = t & 63;
        const float* src = ab ? &sB[s][r * KPAD] : &sA[s][r * KPAD];
        float acc = 0.0f;
        #pragma unroll
        for (int k = 0; k < NPOS; k++)
            acc = fmaf(src[k], src[k], acc);
        if (ab) nB[s][r] = acc; else nA[s][r] = acc;
    }
    __syncthreads();

    float wxv = *wxp;
    float part[16];

    #pragma unroll
    for (int s = 0; s < 2; s++) {
        unsigned long long acc[16];
        #pragma unroll
        for (int u2 = 0; u2 < 16; u2++) acc[u2] = 0ull;

        const float* As = sA[s];
        const float* Bs = sB[s];
        #pragma unroll
        for (int kk = 0; kk < NPOS / 2; kk++) {
            unsigned long long a[4], b[4];
            #pragma unroll
            for (int i = 0; i < 4; i++)
                a[i] = *(const unsigned long long*)(As + (ty + 16 * i) * KPAD + 2 * kk);
            #pragma unroll
            for (int j = 0; j < 4; j++)
                b[j] = *(const unsigned long long*)(Bs + (tx + 16 * j) * KPAD + 2 * kk);
            #pragma unroll
            for (int i = 0; i < 4; i++)
                #pragma unroll
                for (int j = 0; j < 4; j++)
                    acc[i * 4 + j] = fma2(a[i], b[j], acc[i * 4 + j]);
        }

        float scale = s ? (1.0f - wxv) : wxv;
        #pragma unroll
        for (int i = 0; i < 4; i++) {
            float na = nA[s][ty + 16 * i];
            #pragma unroll
            for (int j = 0; j < 4; j++) {
                float2 g = *(float2*)&acc[i * 4 + j];
                float G = g.x + g.y;
                float d2 = fmaf(-2.0f, G, na + nB[s][tx + 16 * j]);
                d2 = fmaxf(d2, 0.0f);
                float d = fsqrt_approx(d2);
                if (s == 0) part[i * 4 + j] = scale * d;
                else        part[i * 4 + j] = fmaf(scale, d, part[i * 4 + j]);
            }
        }
    }

    #pragma unroll
    for (int i = 0; i < 4; i++)
        #pragma unroll
        for (int j = 0; j < 4; j++)
            if (p0 + ty + 16 * i == q0 + tx + 16 * j) part[i * 4 + j] = 0.0f;

    #pragma unroll
    for (int i = 0; i < 4; i++) {
        int p = p0 + ty + 16 * i;
        float* orow = out + ((size_t)bz * SEQ + p) * SEQ;
        #pragma unroll
        for (int j = 0; j < 4; j++)
            orow[q0 + tx + 16 * j] = part[i * 4 + j];
    }

    if (ti != tj) {
        #pragma unroll
        for (int i = 0; i < 4; i++)
            #pragma unroll
            for (int j = 0; j < 4; j++)
                sT[(ty + 16 * i) * 65 + (tx + 16 * j)] = part[i * 4 + j];
        __syncthreads();
        #pragma unroll
        for (int i = 0; i < 4; i++) {
            int q = q0 + ty + 16 * i;
            float* orow = out + ((size_t)bz * SEQ + q) * SEQ;
            #pragma unroll
            for (int j = 0; j < 4; j++)
                orow[p0 + tx + 16 * j] = sT[(tx + 16 * j) * 65 + (ty + 16 * i)];
        }
    }
}

// ---------------------------------------------------------------------------
extern "C" void kernel_launch(void* const* d_in, const int* in_sizes, int n_in,
                              void* d_out, int out_size) {
    const float* query = (const float*)d_in[0];
    const float* attn  = (const float*)d_in[1];
    const float* pex   = (const float*)d_in[2];
    const float* pey   = (const float*)d_in[3];
    const float* wx    = (const float*)d_in[4];
    float* out = (float*)d_out;

    dim3 lgrid(9, BATCH);
    li_kernel<<<lgrid, 256>>>(query, pex, pey);

    scan_kernel<<<13824, 256>>>(attn);

    dim3 dgrid(45, BATCH);
    dist_kernel<<<dgrid, 256>>>(wx, out);
}

// round 4
// speedup vs baseline: 1.0766x; 1.0766x over previous
#include <cuda_runtime.h>

#define NB      8
#define NHEADS  12
#define HH      24
#define SEQ     576
#define DIM     64
#define NPOS    24
#define BATCH   96
#define KPAD    28          // 16B-aligned rows for LDS.128 over k

// Scratch: pe_x_flat / pe_y_flat  [BATCH][SEQ][NPOS]
__device__ __align__(16) float g_Vx[BATCH * SEQ * NPOS];
__device__ __align__(16) float g_Vy[BATCH * SEQ * NPOS];

__device__ __forceinline__ float sigmoidf_(float x) {
    return 1.0f / (1.0f + __expf(-x));
}

__device__ __forceinline__ unsigned long long fma2(unsigned long long a,
                                                   unsigned long long b,
                                                   unsigned long long c) {
    unsigned long long d;
    asm("fma.rn.f32x2 %0, %1, %2, %3;" : "=l"(d) : "l"(a), "l"(b), "l"(c));
    return d;
}

__device__ __forceinline__ unsigned long long pack2(float lo, float hi) {
    unsigned long long r;
    asm("mov.b64 %0, {%1, %2};" : "=l"(r) : "f"(lo), "f"(hi));
    return r;
}

__device__ __forceinline__ float fsqrt_approx(float x) {
    float r;
    asm("sqrt.approx.f32 %0, %1;" : "=f"(r) : "f"(x));
    return r;
}

// ---------------------------------------------------------------------------
// Kernel 1: fused CoPE (R2 structure + GEMM fixes).
// blockIdx.x in [0, 4608): path = blk/2304, id = blk % 2304, id = n*12 + m.
// GEMM phase: 288 (j, p-pair) tasks, 1 fma2 + 2 LDS per d per task.
// ---------------------------------------------------------------------------
__global__ void __launch_bounds__(256) cope_kernel(
    const float* __restrict__ query,      // [8,12,576,64]
    const float* __restrict__ attn,       // [8,12,576,576]
    const float* __restrict__ pex,        // [64,24]
    const float* __restrict__ pey)        // [64,24]
{
    __shared__ float q_s[HH * 65];            // 24 x 64, pad 65
    __shared__ __align__(8) float pe_s[DIM * NPOS];   // 64 x 24
    __shared__ __align__(8) float li[HH * 26];        // logits_int, pad 26 (even)

    int blk  = blockIdx.x;
    int path = (blk >= 2304) ? 1 : 0;
    int id   = blk - path * 2304;
    int n    = id / 12;
    int m    = id % 12;
    // attn-side decomposition (faithful to reshape-without-permute)
    int b_a  = id / 288;
    int hd_a = (id / 24) % 12;
    int r_a  = id % 24;
    // query-side decomposition
    int b_q  = n / 24;
    int s_q  = n % 24;

    int t = threadIdx.x;

    const float* pe = path ? pey : pex;
    for (int idx = t; idx < DIM * NPOS; idx += 256)
        pe_s[idx] = pe[idx];

    if (!path) {
        const float* qb = query + (((size_t)(b_q * 12 + m)) * SEQ + s_q * 24) * DIM;
        for (int idx = t; idx < HH * DIM; idx += 256) {
            int rr = idx >> 6, d = idx & 63;
            q_s[rr * 65 + d] = qb[idx];
        }
    } else {
        const float* qb = query + (((size_t)(b_q * 12 + m)) * SEQ + s_q) * DIM;
        for (int idx = t; idx < HH * DIM; idx += 256) {
            int rr = idx >> 6, d = idx & 63;
            q_s[rr * 65 + d] = qb[(size_t)rr * (24 * DIM) + d];
        }
    }
    __syncthreads();

    // GEMM: 288 tasks = 24 j x 12 p-pairs; one fma2 per d.
    for (int o = t; o < HH * 12; o += 256) {
        int j  = o / 12;
        int pp = o - j * 12;
        const float* qr = q_s + j * 65;
        const float* pr = pe_s + 2 * pp;
        unsigned long long acc = 0ull;
        #pragma unroll
        for (int d = 0; d < DIM; d++) {
            float q = qr[d];
            float2 pv = *(const float2*)(pr + d * NPOS);
            acc = fma2(pack2(q, q), pack2(pv.x, pv.y), acc);
        }
        *(float2*)(li + j * 26 + 2 * pp) = *(float2*)&acc;
    }
    __syncthreads();

    // Phase C: warp-per-row suffix scan. 8 warps cover 24 rows in 3 passes.
    int warp = t >> 5, lane = t & 31;
    int bh = b_q * 12 + m;
    for (int j = warp; j < HH; j += 8) {
        const float* arow;
        int astride;
        float* dst;
        if (!path) {
            arow = attn + (((size_t)(b_a * 12 + hd_a)) * SEQ + (size_t)(r_a * 24 + j)) * SEQ
                        + (size_t)(r_a * 24);
            astride = 1;
            dst = g_Vx + ((size_t)bh * SEQ + (size_t)(s_q * 24 + j)) * NPOS;
        } else {
            arow = attn + (((size_t)(b_a * 12 + hd_a)) * SEQ + (size_t)(j * 24 + r_a)) * SEQ
                        + (size_t)r_a;
            astride = 24;
            dst = g_Vy + ((size_t)bh * SEQ + (size_t)(j * 24 + s_q)) * NPOS;
        }
        float v = 0.0f;
        if (lane < NPOS)
            v = sigmoidf_(arow[lane * astride]);
        #pragma unroll
        for (int d = 1; d < 32; d <<= 1) {
            float tv = __shfl_down_sync(0xffffffffu, v, d);
            if (lane + d < NPOS) v += tv;
        }
        if (lane < NPOS) {
            float pp = fminf(v, (float)(NPOS - 1));
            float pf = floorf(pp);
            int   ifl = (int)pf;
            int   ic  = (int)ceilf(pp);
            float w   = pp - pf;
            float val = li[j * 26 + ic] * w + li[j * 26 + ifl] * (1.0f - w);
            dst[lane] = val;
        }
    }
}

// ---------------------------------------------------------------------------
// Kernel 2: fused double-cdist + mix, symmetric tiles, LDS.128 k-vectorized.
// grid (45, 96); block 256 = 16x16; 4x4 strided micro-tile.
// ---------------------------------------------------------------------------
union DistSm {
    struct { float A[2][64 * KPAD]; float B[2][64 * KPAD]; } m;
    float T[64 * 65];
};

__global__ void __launch_bounds__(256, 3) dist_kernel(
    const float* __restrict__ wxp,
    float* __restrict__ out)
{
    __shared__ __align__(16) DistSm sm;
    __shared__ float nA[2][64];
    __shared__ float nB[2][64];

    int bz = blockIdx.y;
    int u = blockIdx.x;
    int ti = 0;
    #pragma unroll 1
    while (u >= (9 - ti)) { u -= (9 - ti); ti++; }
    int tj = ti + u;
    int p0 = ti * 64;
    int q0 = tj * 64;

    int t  = threadIdx.x;
    int tx = t & 15;
    int ty = t >> 4;

    // Load 64x24 row blocks; rows padded to 28 (16B-aligned) -> STS.128
    #pragma unroll
    for (int s = 0; s < 2; s++) {
        const float* V = s ? g_Vy : g_Vx;
        const float4* ga = (const float4*)(V + ((size_t)bz * SEQ + p0) * NPOS);
        const float4* gb = (const float4*)(V + ((size_t)bz * SEQ + q0) * NPOS);
        for (int idx = t; idx < 64 * NPOS / 4; idx += 256) {   // 384 float4
            float4 va = ga[idx];
            float4 vb = gb[idx];
            int r = idx / 6, c = (idx - r * 6) * 4;
            *(float4*)(&sm.m.A[s][r * KPAD + c]) = va;
            *(float4*)(&sm.m.B[s][r * KPAD + c]) = vb;
        }
    }
    __syncthreads();

    // Row norms
    {
        int s  = (t >> 7) & 1;
        int ab = (t >> 6) & 1;
        int r  = t & 63;
        const float* src = ab ? &sm.m.B[s][r * KPAD] : &sm.m.A[s][r * KPAD];
        float acc = 0.0f;
        #pragma unroll
        for (int k = 0; k < NPOS; k++)
            acc = fmaf(src[k], src[k], acc);
        if (ab) nB[s][r] = acc; else nA[s][r] = acc;
    }
    __syncthreads();

    float wxv = *wxp;
    float part[16];

    #pragma unroll
    for (int s = 0; s < 2; s++) {
        unsigned long long acc[16];
        #pragma unroll
        for (int u2 = 0; u2 < 16; u2++) acc[u2] = 0ull;

        const float* As = sm.m.A[s];
        const float* Bs = sm.m.B[s];
        #pragma unroll
        for (int k4 = 0; k4 < NPOS / 4; k4++) {
            float4 a4[4], b4[4];
            #pragma unroll
            for (int i = 0; i < 4; i++)
                a4[i] = *(const float4*)(As + (ty + 16 * i) * KPAD + 4 * k4);
            #pragma unroll
            for (int j = 0; j < 4; j++)
                b4[j] = *(const float4*)(Bs + (tx + 16 * j) * KPAD + 4 * k4);
            #pragma unroll
            for (int i = 0; i < 4; i++) {
                unsigned long long alo = pack2(a4[i].x, a4[i].y);
                unsigned long long ahi = pack2(a4[i].z, a4[i].w);
                #pragma unroll
                for (int j = 0; j < 4; j++) {
                    acc[i * 4 + j] = fma2(alo, pack2(b4[j].x, b4[j].y), acc[i * 4 + j]);
                    acc[i * 4 + j] = fma2(ahi, pack2(b4[j].z, b4[j].w), acc[i * 4 + j]);
                }
            }
        }

        float scale = s ? (1.0f - wxv) : wxv;
        #pragma unroll
        for (int i = 0; i < 4; i++) {
            float na = nA[s][ty + 16 * i];
            #pragma unroll
            for (int j = 0; j < 4; j++) {
                float2 g = *(float2*)&acc[i * 4 + j];
                float G = g.x + g.y;
                float d2 = fmaf(-2.0f, G, na + nB[s][tx + 16 * j]);
                d2 = fmaxf(d2, 0.0f);
                float d = fsqrt_approx(d2);
                if (s == 0) part[i * 4 + j] = scale * d;
                else        part[i * 4 + j] = fmaf(scale, d, part[i * 4 + j]);
            }
        }
    }

    // Exact-zero diagonal
    #pragma unroll
    for (int i = 0; i < 4; i++)
        #pragma unroll
        for (int j = 0; j < 4; j++)
            if (p0 + ty + 16 * i == q0 + tx + 16 * j) part[i * 4 + j] = 0.0f;

    // Primary tile write
    #pragma unroll
    for (int i = 0; i < 4; i++) {
        int p = p0 + ty + 16 * i;
        float* orow = out + ((size_t)bz * SEQ + p) * SEQ;
        #pragma unroll
        for (int j = 0; j < 4; j++)
            orow[q0 + tx + 16 * j] = part[i * 4 + j];
    }

    // Mirror tile via smem transpose (overlaid on A/B)
    if (ti != tj) {
        __syncthreads();   // everyone done reading A/B
        #pragma unroll
        for (int i = 0; i < 4; i++)
            #pragma unroll
            for (int j = 0; j < 4; j++)
                sm.T[(ty + 16 * i) * 65 + (tx + 16 * j)] = part[i * 4 + j];
        __syncthreads();
        #pragma unroll
        for (int i = 0; i < 4; i++) {
            int q = q0 + ty + 16 * i;
            float* orow = out + ((size_t)bz * SEQ + q) * SEQ;
            #pragma unroll
            for (int j = 0; j < 4; j++)
                orow[p0 + tx + 16 * j] = sm.T[(tx + 16 * j) * 65 + (ty + 16 * i)];
        }
    }
}

// ---------------------------------------------------------------------------
extern "C" void kernel_launch(void* const* d_in, const int* in_sizes, int n_in,
                              void* d_out, int out_size) {
    const float* query = (const float*)d_in[0];
    const float* attn  = (const float*)d_in[1];
    const float* pex   = (const float*)d_in[2];
    const float* pey   = (const float*)d_in[3];
    const float* wx    = (const float*)d_in[4];
    float* out = (float*)d_out;

    cope_kernel<<<4608, 256>>>(query, attn, pex, pey);

    dim3 dgrid(45, BATCH);
    dist_kernel<<<dgrid, 256>>>(wx, out);
}